// round 8
// baseline (speedup 1.0000x reference)
#include <cuda_runtime.h>
#include <math.h>

// SoftSkeletonLoss reduces analytically:
//  - soft_skeletonize(sigmoid-range input) == 0 after iteration 1 (conv3x3x3 of a
//    strictly positive field is > 0 -> eroded = opened = 1 -> skeleton = clip(x-1,0,1)=0),
//    so skeleton_loss = 1 - EPS/EPS = 0 exactly.
//  - Remaining: connectivity_loss = |comp_p - comp_t| where
//      comp = cnt / mean_nb,  mean_nb = (sum_masked(conv3x3x3(field)) + EPS*cnt) / max(cnt,1)
//    pred:   field = (pred > 0) binarized (sigmoid(x)>0.5 <=> x>0), mask = pred>0
//    target: field = target raw,                                     mask = target>0
//
// Fused 27-point box-sum reduction. Loader==compute role fusion (centers come free
// from the loader's registers), x-halo via warp shuffles, separable x-presums in
// smem, z-sweep with register rings, loads pipelined one plane ahead, last-block
// finalize with replay-safe reset.

#define DIMV   192
#define PLANE  (DIMV * DIMV)
#define TILE   32
#define CHUNK  48
#define NBLK   (6 * 6 * 16)     // 576 blocks
#define NTHR   288

// cnt_p, sum_p, cnt_t, sum_t (zero at module load; reset by last block each replay)
__device__ double   g_acc[4];
__device__ unsigned g_ticket;

__global__ __launch_bounds__(NTHR, 4)
void fused_skel_kernel(const float* __restrict__ pred,
                       const float* __restrict__ target,
                       float* __restrict__ out, int out_size) {
    __shared__ float sxs[2][34 * 32];   // 3-wide x-presums, 34 halo rows x 32 cols
    __shared__ float red[9][2];

    const int tid = threadIdx.x;
    const int bx0 = blockIdx.x * TILE;
    const int by0 = blockIdx.y * TILE;

    const int  zc     = blockIdx.z;            // 0..15
    const bool isPred = (zc < 8);
    const int  s      = isPred ? zc : zc - 8;  // 0..7
    const int  n      = s >> 2;                // sample 0..1
    const int  z0     = (s & 3) * CHUNK;
    const int  zE     = z0 + CHUNK;

    const float* __restrict__ src =
        (isPred ? pred : target) + (size_t)n * ((size_t)DIMV * PLANE);

    // ---- loader identity (fused with compute: tid<256 loads its own center row) ----
    int ly, jj; bool lact;
    if (tid < 256)      { ly = (tid >> 3) + 1; jj = tid & 7; lact = true; }
    else if (tid < 272) { int u = tid - 256; ly = (u < 8) ? 0 : 33; jj = u & 7; lact = true; }
    else                { ly = 1; jj = 0; lact = false; }

    const int  gy    = by0 + ly - 1;
    const bool rowIn = lact && ((unsigned)gy < (unsigned)DIMV);
    const bool hasL  = (bx0 > 0);
    const bool hasR  = (bx0 + TILE < DIMV);
    const int  xsOff = ly * 32 + 4 * jj;

    // running plane pointer (never dereferenced when !rowIn / !zin)
    const float* lp = src + (long long)(z0 - 1) * PLANE + gy * DIMV + (bx0 + 4 * jj);

    float4 v;          // raw 4 values of this lane's halo-row chunk, current fetch
    float  e0, e1;     // left/right x-halo values

    // fetch plane zp into (v,e0,e1); x-halo via intra-warp shuffle (rows of 8
    // lanes are warp-aligned); boundary lanes jj==0/7 do one predicated scalar LDG.
    auto fetch = [&](int zp) {
        const bool zin = ((unsigned)zp < (unsigned)DIMV);
        float4 t = make_float4(0.f, 0.f, 0.f, 0.f);
        float  l = 0.f, r = 0.f;
        if (rowIn && zin) {
            t = *(const float4*)lp;
            if (jj == 0)      { if (hasL) l = lp[-1]; }
            else if (jj == 7) { if (hasR) r = lp[4]; }
        }
        lp += PLANE;
        float up = __shfl_up_sync(0xffffffffu, t.w, 1);   // neighbor col gx0-1
        float dn = __shfl_down_sync(0xffffffffu, t.x, 1); // neighbor col gx0+4
        v  = t;
        e0 = (jj == 0) ? l : up;
        e1 = (jj == 7) ? r : dn;
    };

    // binarize (pred) and store 3-wide x-sums for this halo row
    auto store_xs = [&](int buf) {
        if (!lact) return;
        float a0, a1, a2, a3, b0, b1;
        if (isPred) {
            a0 = v.x > 0.f ? 1.f : 0.f; a1 = v.y > 0.f ? 1.f : 0.f;
            a2 = v.z > 0.f ? 1.f : 0.f; a3 = v.w > 0.f ? 1.f : 0.f;
            b0 = e0  > 0.f ? 1.f : 0.f; b1 = e1  > 0.f ? 1.f : 0.f;
        } else { a0 = v.x; a1 = v.y; a2 = v.z; a3 = v.w; b0 = e0; b1 = e1; }
        float4 xs = make_float4(b0 + a0 + a1, a0 + a1 + a2,
                                a1 + a2 + a3, a2 + a3 + b1);
        *(float4*)&sxs[buf][xsOff] = xs;
    };

    // ---- compute identity: tid<256, ty=tid>>3 (== ly-1), tx=tid&7 (== jj) ----
    const int ty = tid >> 3;
    const int tx = tid & 7;
    auto psum = [&](int buf) -> float4 {
        if (tid >= 256) return make_float4(0.f, 0.f, 0.f, 0.f);
        float4 a = *(const float4*)&sxs[buf][(ty    ) * 32 + 4 * tx];
        float4 b = *(const float4*)&sxs[buf][(ty + 1) * 32 + 4 * tx];
        float4 c = *(const float4*)&sxs[buf][(ty + 2) * 32 + 4 * tx];
        return make_float4(a.x + b.x + c.x, a.y + b.y + c.y,
                           a.z + b.z + c.z, a.w + b.w + c.w);
    };

    // ---- prologue: planes z0-1 -> buf0, z0 -> buf1, prefetch z0+1 ----
    fetch(z0 - 1);
    store_xs(0);
    fetch(z0);
    __syncthreads();
    float4 pPrev = psum(0);
    float4 cCur  = v;              // raw centers of plane z0 (tid<256)
    store_xs(1);
    fetch(z0 + 1);
    __syncthreads();
    float4 pCur = psum(1);

    float cnt = 0.f, sum = 0.f;

    // ---- main sweep: regs hold plane z+1; fetch z+2 while computing z ----
    #pragma unroll 6
    for (int z = z0; z < zE; ++z) {
        const int buf = (z - z0) & 1;        // destination of plane z+1
        float4 cNext = v;                    // centers of plane z+1
        store_xs(buf);
        fetch(z + 2);                        // zin predicate handles z+2 > 191
        __syncthreads();
        float4 pNext = psum(buf);

        if (tid < 256) {
            if (cCur.x > 0.f) { cnt += 1.f; sum += pPrev.x + pCur.x + pNext.x; }
            if (cCur.y > 0.f) { cnt += 1.f; sum += pPrev.y + pCur.y + pNext.y; }
            if (cCur.z > 0.f) { cnt += 1.f; sum += pPrev.z + pCur.z + pNext.z; }
            if (cCur.w > 0.f) { cnt += 1.f; sum += pPrev.w + pCur.w + pNext.w; }
        }
        pPrev = pCur; pCur = pNext; cCur = cNext;
    }

    // ---- block reduction (9 warps) ----
    #pragma unroll
    for (int o = 16; o; o >>= 1) {
        cnt += __shfl_down_sync(0xffffffffu, cnt, o);
        sum += __shfl_down_sync(0xffffffffu, sum, o);
    }
    const int wid  = tid >> 5;
    const int lane = tid & 31;
    if (lane == 0) { red[wid][0] = cnt; red[wid][1] = sum; }
    __syncthreads();

    if (tid == 0) {
        float c2 = 0.f, s2 = 0.f;
        #pragma unroll
        for (int w = 0; w < 9; ++w) { c2 += red[w][0]; s2 += red[w][1]; }
        const int ai = isPred ? 0 : 2;
        atomicAdd(&g_acc[ai],     (double)c2);
        atomicAdd(&g_acc[ai + 1], (double)s2);
        __threadfence();
        unsigned t = atomicAdd(&g_ticket, 1u);
        if (t == NBLK - 1) {
            // last block: finalize, write output, reset for next graph replay
            __threadfence();
            double cp = atomicAdd(&g_acc[0], 0.0);
            double sp = atomicAdd(&g_acc[1], 0.0);
            double ct = atomicAdd(&g_acc[2], 0.0);
            double st = atomicAdd(&g_acc[3], 0.0);
            const double eps = 1e-8;
            double mean_p = (sp + eps * cp) / fmax(cp, 1.0);
            double mean_t = (st + eps * ct) / fmax(ct, 1.0);
            double comp_p = cp / mean_p;
            double comp_t = ct / mean_t;
            float loss = (float)fabs(comp_p - comp_t);  // skeleton_loss == 0 exactly
            for (int i = 0; i < out_size; ++i) out[i] = loss;
            g_acc[0] = 0.0; g_acc[1] = 0.0; g_acc[2] = 0.0; g_acc[3] = 0.0;
            __threadfence();
            g_ticket = 0u;
        }
    }
}

extern "C" void kernel_launch(void* const* d_in, const int* in_sizes, int n_in,
                              void* d_out, int out_size) {
    const float* pred   = (const float*)d_in[0];
    const float* target = (const float*)d_in[1];

    dim3 grid(DIMV / TILE, DIMV / TILE, 16);   // 6 x 6 x 16 = 576 blocks
    fused_skel_kernel<<<grid, NTHR>>>(pred, target, (float*)d_out, out_size);
}

// round 9
// speedup vs baseline: 1.1932x; 1.1932x over previous
#include <cuda_runtime.h>
#include <math.h>

// SoftSkeletonLoss reduces analytically:
//  - soft_skeletonize(sigmoid-range input) == 0 after iteration 1 (conv3x3x3 of a
//    strictly positive field is > 0 -> eroded = opened = 1 -> skeleton = clip(x-1,0,1)=0),
//    so skeleton_loss = 1 - EPS/EPS = 0 exactly.
//  - Remaining: connectivity_loss = |comp_p - comp_t| where
//      comp = cnt / mean_nb,  mean_nb = (sum_masked(conv3x3x3(field)) + EPS*cnt) / max(cnt,1)
//    pred:   field = (pred > 0) binarized (sigmoid(x)>0.5 <=> x>0), mask = pred>0
//    target: field = target raw,                                     mask = target>0
//
// Fused 27-point box-sum reduction. Loader==compute role fusion (centers come free
// from the loader's registers), x-halo via warp shuffles AT CONSUME TIME (fetch is
// pure issue so the one-plane-ahead prefetch actually hides DRAM latency),
// separable x-presums in smem, z-sweep register rings, last-block finalize.

#define DIMV   192
#define PLANE  (DIMV * DIMV)
#define TILE   32
#define CHUNK  48
#define NBLK   (6 * 6 * 16)     // 576 blocks
#define NTHR   288

// cnt_p, sum_p, cnt_t, sum_t (zero at module load; reset by last block each replay)
__device__ double   g_acc[4];
__device__ unsigned g_ticket;

__global__ __launch_bounds__(NTHR, 4)
void fused_skel_kernel(const float* __restrict__ pred,
                       const float* __restrict__ target,
                       float* __restrict__ out, int out_size) {
    __shared__ float sxs[2][34 * 32];   // 3-wide x-presums, 34 halo rows x 32 cols
    __shared__ float red[9][2];

    const int tid = threadIdx.x;
    const int bx0 = blockIdx.x * TILE;
    const int by0 = blockIdx.y * TILE;

    const int  zc     = blockIdx.z;            // 0..15
    const bool isPred = (zc < 8);
    const int  s      = isPred ? zc : zc - 8;  // 0..7
    const int  n      = s >> 2;                // sample 0..1
    const int  z0     = (s & 3) * CHUNK;
    const int  zE     = z0 + CHUNK;

    const float* __restrict__ src =
        (isPred ? pred : target) + (size_t)n * ((size_t)DIMV * PLANE);

    // ---- loader identity (fused with compute: tid<256 loads its own center row) ----
    int ly, jj; bool lact;
    if (tid < 256)      { ly = (tid >> 3) + 1; jj = tid & 7; lact = true; }
    else if (tid < 272) { int u = tid - 256; ly = (u < 8) ? 0 : 33; jj = u & 7; lact = true; }
    else                { ly = 1; jj = 0; lact = false; }

    const int  gy    = by0 + ly - 1;
    const bool rowIn = lact && ((unsigned)gy < (unsigned)DIMV);
    const bool ldL   = (jj == 0) && (bx0 > 0);
    const bool ldR   = (jj == 7) && (bx0 + TILE < DIMV);
    const int  xsOff = ly * 32 + 4 * jj;

    // running plane pointer (never dereferenced when !rowIn / !zin)
    const float* lp = src + (long long)(z0 - 1) * PLANE + gy * DIMV + (bx0 + 4 * jj);

    float4 v;            // raw chunk of the most recently fetched plane
    float  le, re;       // boundary-lane edge scalars (only meaningful jj==0/7)

    // PURE-ISSUE fetch: LDG + predicated boundary scalars + pointer bump.
    // Nothing consumes the loaded registers here -> latency hidden by the
    // plane of work between fetch and store_xs.
    auto fetch = [&](int zp) {
        const bool a = rowIn && ((unsigned)zp < (unsigned)DIMV);
        v = make_float4(0.f, 0.f, 0.f, 0.f); le = 0.f; re = 0.f;
        if (a) {
            v = *(const float4*)lp;
            if (ldL) le = lp[-1];
            if (ldR) re = lp[4];
        }
        lp += PLANE;
    };

    // Consume-time: x-halo via intra-warp shuffles (rows of 8 lanes are
    // warp-aligned; group-crossing lanes jj==0/7 use the edge scalars),
    // binarize (pred), store 3-wide x-sums for this halo row.
    auto store_xs = [&](int buf) {
        float up = __shfl_up_sync(0xffffffffu, v.w, 1);   // col gx0-1
        float dn = __shfl_down_sync(0xffffffffu, v.x, 1); // col gx0+4
        if (!lact) return;
        float e0 = (jj == 0) ? le : up;
        float e1 = (jj == 7) ? re : dn;
        float a0, a1, a2, a3, b0, b1;
        if (isPred) {
            a0 = v.x > 0.f ? 1.f : 0.f; a1 = v.y > 0.f ? 1.f : 0.f;
            a2 = v.z > 0.f ? 1.f : 0.f; a3 = v.w > 0.f ? 1.f : 0.f;
            b0 = e0  > 0.f ? 1.f : 0.f; b1 = e1  > 0.f ? 1.f : 0.f;
        } else { a0 = v.x; a1 = v.y; a2 = v.z; a3 = v.w; b0 = e0; b1 = e1; }
        float4 xs = make_float4(b0 + a0 + a1, a0 + a1 + a2,
                                a1 + a2 + a3, a2 + a3 + b1);
        *(float4*)&sxs[buf][xsOff] = xs;
    };

    // ---- compute identity: tid<256, ty=tid>>3 (== ly-1), tx=tid&7 (== jj) ----
    const int ty = tid >> 3;
    const int tx = tid & 7;
    auto psum = [&](int buf) -> float4 {
        if (tid >= 256) return make_float4(0.f, 0.f, 0.f, 0.f);
        float4 a = *(const float4*)&sxs[buf][(ty    ) * 32 + 4 * tx];
        float4 b = *(const float4*)&sxs[buf][(ty + 1) * 32 + 4 * tx];
        float4 c = *(const float4*)&sxs[buf][(ty + 2) * 32 + 4 * tx];
        return make_float4(a.x + b.x + c.x, a.y + b.y + c.y,
                           a.z + b.z + c.z, a.w + b.w + c.w);
    };

    // ---- prologue: planes z0-1 -> buf0, z0 -> buf1, prefetch z0+1 ----
    fetch(z0 - 1);
    store_xs(0);                    // (first store consumes immediately; one-off)
    fetch(z0);
    __syncthreads();
    float4 pPrev = psum(0);
    float4 cCur  = v;               // raw centers of plane z0 (tid<256: ly = ty+1)
    store_xs(1);
    fetch(z0 + 1);
    __syncthreads();
    float4 pCur = psum(1);

    float cnt = 0.f, sum = 0.f;

    // ---- main sweep: regs hold plane z+1; fetch z+2 while computing z ----
    #pragma unroll 2
    for (int z = z0; z < zE; ++z) {
        const int buf = (z - z0) & 1;        // destination of plane z+1
        float4 cNext = v;                    // centers of plane z+1 (before overwrite)
        store_xs(buf);                       // consume plane z+1 (fetched last iter)
        fetch(z + 2);                        // pure issue; zin handles z+2 > 191
        __syncthreads();
        float4 pNext = psum(buf);

        if (tid < 256) {
            if (cCur.x > 0.f) { cnt += 1.f; sum += pPrev.x + pCur.x + pNext.x; }
            if (cCur.y > 0.f) { cnt += 1.f; sum += pPrev.y + pCur.y + pNext.y; }
            if (cCur.z > 0.f) { cnt += 1.f; sum += pPrev.z + pCur.z + pNext.z; }
            if (cCur.w > 0.f) { cnt += 1.f; sum += pPrev.w + pCur.w + pNext.w; }
        }
        pPrev = pCur; pCur = pNext; cCur = cNext;
    }

    // ---- block reduction (9 warps) ----
    #pragma unroll
    for (int o = 16; o; o >>= 1) {
        cnt += __shfl_down_sync(0xffffffffu, cnt, o);
        sum += __shfl_down_sync(0xffffffffu, sum, o);
    }
    const int wid  = tid >> 5;
    const int lane = tid & 31;
    if (lane == 0) { red[wid][0] = cnt; red[wid][1] = sum; }
    __syncthreads();

    if (tid == 0) {
        float c2 = 0.f, s2 = 0.f;
        #pragma unroll
        for (int w = 0; w < 9; ++w) { c2 += red[w][0]; s2 += red[w][1]; }
        const int ai = isPred ? 0 : 2;
        atomicAdd(&g_acc[ai],     (double)c2);
        atomicAdd(&g_acc[ai + 1], (double)s2);
        __threadfence();
        unsigned t = atomicAdd(&g_ticket, 1u);
        if (t == NBLK - 1) {
            // last block: finalize, write output, reset for next graph replay
            __threadfence();
            double cp = atomicAdd(&g_acc[0], 0.0);
            double sp = atomicAdd(&g_acc[1], 0.0);
            double ct = atomicAdd(&g_acc[2], 0.0);
            double st = atomicAdd(&g_acc[3], 0.0);
            const double eps = 1e-8;
            double mean_p = (sp + eps * cp) / fmax(cp, 1.0);
            double mean_t = (st + eps * ct) / fmax(ct, 1.0);
            double comp_p = cp / mean_p;
            double comp_t = ct / mean_t;
            float loss = (float)fabs(comp_p - comp_t);  // skeleton_loss == 0 exactly
            for (int i = 0; i < out_size; ++i) out[i] = loss;
            g_acc[0] = 0.0; g_acc[1] = 0.0; g_acc[2] = 0.0; g_acc[3] = 0.0;
            __threadfence();
            g_ticket = 0u;
        }
    }
}

extern "C" void kernel_launch(void* const* d_in, const int* in_sizes, int n_in,
                              void* d_out, int out_size) {
    const float* pred   = (const float*)d_in[0];
    const float* target = (const float*)d_in[1];

    dim3 grid(DIMV / TILE, DIMV / TILE, 16);   // 6 x 6 x 16 = 576 blocks
    fused_skel_kernel<<<grid, NTHR>>>(pred, target, (float*)d_out, out_size);
}

// round 10
// speedup vs baseline: 1.2531x; 1.0502x over previous
#include <cuda_runtime.h>
#include <math.h>

// SoftSkeletonLoss reduces analytically:
//  - soft_skeletonize(sigmoid-range input) == 0 after iteration 1 (conv3x3x3 of a
//    strictly positive field is > 0 -> eroded = opened = 1 -> skeleton = clip(x-1,0,1)=0),
//    so skeleton_loss = 1 - EPS/EPS = 0 exactly.
//  - Remaining: connectivity_loss = |comp_p - comp_t| where
//      comp = cnt / mean_nb,  mean_nb = (sum_masked(conv3x3x3(field)) + EPS*cnt) / max(cnt,1)
//    pred:   field = (pred > 0) binarized (sigmoid(x)>0.5 <=> x>0), mask = pred>0
//    target: field = target raw,                                     mask = target>0
//
// Fused 27-point box-sum reduction. TWO z-planes per barrier (25 BARs/block, MLP=2
// prefetch), loader==compute role fusion (centers free from loader registers, kept
// as 4-bit masks), x-halo via warp shuffles at consume time, separable x-presums
// in smem, last-block finalize with replay-safe reset.

#define DIMV   192
#define PLANE  (DIMV * DIMV)
#define TILE   32
#define CHUNK  48
#define NBLK   (6 * 6 * 16)     // 576 blocks
#define NTHR   288
#define SP     (34 * 32)        // one xs plane: 34 halo rows x 32 cols

// cnt_p, sum_p, cnt_t, sum_t (zero at module load; reset by last block each replay)
__device__ double   g_acc[4];
__device__ unsigned g_ticket;

__global__ __launch_bounds__(NTHR, 4)
void fused_skel_kernel(const float* __restrict__ pred,
                       const float* __restrict__ target,
                       float* __restrict__ out, int out_size) {
    __shared__ float sxs[2][2][SP];   // [buf][plane][row*32+col]
    __shared__ float red[9][2];

    const int tid = threadIdx.x;
    const int bx0 = blockIdx.x * TILE;
    const int by0 = blockIdx.y * TILE;

    const int  zc     = blockIdx.z;            // 0..15
    const bool isPred = (zc < 8);
    const int  s      = isPred ? zc : zc - 8;  // 0..7
    const int  n      = s >> 2;                // sample 0..1
    const int  z0     = (s & 3) * CHUNK;

    const float* __restrict__ src =
        (isPred ? pred : target) + (size_t)n * ((size_t)DIMV * PLANE);

    // ---- loader identity (tid<256 loads its own center row ly = ty+1) ----
    int ly, jj; bool lact;
    if (tid < 256)      { ly = (tid >> 3) + 1; jj = tid & 7; lact = true; }
    else if (tid < 272) { int u = tid - 256; ly = (u < 8) ? 0 : 33; jj = u & 7; lact = true; }
    else                { ly = 1; jj = 0; lact = false; }

    const int  gy    = by0 + ly - 1;
    const bool rowIn = lact && ((unsigned)gy < (unsigned)DIMV);
    // single boundary-edge scalar per lane (jj==0 -> left, jj==7 -> right)
    const bool ldE   = ((jj == 0) && (bx0 > 0)) || ((jj == 7) && (bx0 + TILE < DIMV));
    const int  eOff  = (jj == 0) ? -1 : 4;
    const int  xsOff = ly * 32 + 4 * jj;

    // running pointer at plane zf (first plane of next fetch pair)
    int zf = z0 - 1;
    const float* lp = src + (long long)zf * PLANE + gy * DIMV + (bx0 + 4 * jj);

    float4 v0, v1;        // raw chunks of the two most recently fetched planes
    float  e0, e1;        // their boundary edge scalars

    // PURE-ISSUE fetch of planes zf, zf+1 (nothing consumes results here)
    auto fetch2 = [&]() {
        const bool a0 = rowIn && ((unsigned)zf       < (unsigned)DIMV);
        const bool a1 = rowIn && ((unsigned)(zf + 1) < (unsigned)DIMV);
        v0 = make_float4(0.f, 0.f, 0.f, 0.f); e0 = 0.f;
        v1 = make_float4(0.f, 0.f, 0.f, 0.f); e1 = 0.f;
        if (a0) { v0 = *(const float4*)lp; if (ldE) e0 = lp[eOff]; }
        if (a1) { const float* q = lp + PLANE;
                  v1 = *(const float4*)q; if (ldE) e1 = q[eOff]; }
        lp += 2 * PLANE; zf += 2;
    };

    // consume-time: x-halo shuffles + binarize (pred) + store 3-wide x-sums
    auto store_xs = [&](const float4& v, float e, float* dst) {
        float up = __shfl_up_sync(0xffffffffu, v.w, 1);   // col gx0-1
        float dn = __shfl_down_sync(0xffffffffu, v.x, 1); // col gx0+4
        if (!lact) return;
        float el = (jj == 0) ? e : up;
        float er = (jj == 7) ? e : dn;
        float a0, a1, a2, a3, b0, b1;
        if (isPred) {
            a0 = v.x > 0.f ? 1.f : 0.f; a1 = v.y > 0.f ? 1.f : 0.f;
            a2 = v.z > 0.f ? 1.f : 0.f; a3 = v.w > 0.f ? 1.f : 0.f;
            b0 = el  > 0.f ? 1.f : 0.f; b1 = er  > 0.f ? 1.f : 0.f;
        } else { a0 = v.x; a1 = v.y; a2 = v.z; a3 = v.w; b0 = el; b1 = er; }
        float4 xs = make_float4(b0 + a0 + a1, a0 + a1 + a2,
                                a1 + a2 + a3, a2 + a3 + b1);
        *(float4*)(dst + xsOff) = xs;
    };

    // center mask: 4 voxels of this compute thread (its own loaded chunk)
    auto mask4 = [&](const float4& c) -> int {
        return (c.x > 0.f ? 1 : 0) | (c.y > 0.f ? 2 : 0) |
               (c.z > 0.f ? 4 : 0) | (c.w > 0.f ? 8 : 0);
    };

    // ---- compute identity: tid<256, ty = tid>>3 (== ly-1), tx = tid&7 (== jj) ----
    const int ty = tid >> 3;
    const int tx = tid & 7;
    auto psum = [&](const float* sp) -> float4 {
        if (tid >= 256) return make_float4(0.f, 0.f, 0.f, 0.f);
        float4 a = *(const float4*)(sp + (ty    ) * 32 + 4 * tx);
        float4 b = *(const float4*)(sp + (ty + 1) * 32 + 4 * tx);
        float4 c = *(const float4*)(sp + (ty + 2) * 32 + 4 * tx);
        return make_float4(a.x + b.x + c.x, a.y + b.y + c.y,
                           a.z + b.z + c.z, a.w + b.w + c.w);
    };

    // ---- prologue: planes z0-1, z0 -> buf0; prefetch z0+1, z0+2 ----
    fetch2();
    store_xs(v0, e0, sxs[0][0]);
    store_xs(v1, e1, sxs[0][1]);
    int mA = mask4(v1);               // centers of plane z0
    fetch2();
    __syncthreads();
    float4 pA = psum(sxs[0][0]);      // P(z0-1)
    float4 pB = psum(sxs[0][1]);      // P(z0)

    float cnt = 0.f, sum = 0.f;

    // ---- main sweep: iteration k handles voxels z0+2k, z0+2k+1 ----
    #pragma unroll 2
    for (int k = 0; k < CHUNK / 2; ++k) {
        const int b = (k + 1) & 1;            // destination buffer
        const int mB = mask4(v0);             // centers plane z+1
        const int mC = mask4(v1);             // centers plane z+2
        store_xs(v0, e0, sxs[b][0]);          // xs of plane z+1
        store_xs(v1, e1, sxs[b][1]);          // xs of plane z+2
        if (k != CHUNK / 2 - 1) fetch2();     // prefetch planes z+3, z+4
        __syncthreads();
        float4 pC = psum(sxs[b][0]);          // P(z+1)
        float4 pD = psum(sxs[b][1]);          // P(z+2)

        if (tid < 256) {
            // voxel plane z (mask mA): needs pA+pB+pC
            if (mA & 1) { cnt += 1.f; sum += pA.x + pB.x + pC.x; }
            if (mA & 2) { cnt += 1.f; sum += pA.y + pB.y + pC.y; }
            if (mA & 4) { cnt += 1.f; sum += pA.z + pB.z + pC.z; }
            if (mA & 8) { cnt += 1.f; sum += pA.w + pB.w + pC.w; }
            // voxel plane z+1 (mask mB): needs pB+pC+pD
            if (mB & 1) { cnt += 1.f; sum += pB.x + pC.x + pD.x; }
            if (mB & 2) { cnt += 1.f; sum += pB.y + pC.y + pD.y; }
            if (mB & 4) { cnt += 1.f; sum += pB.z + pC.z + pD.z; }
            if (mB & 8) { cnt += 1.f; sum += pB.w + pC.w + pD.w; }
        }
        pA = pC; pB = pD; mA = mC;
    }

    // ---- block reduction (9 warps) ----
    #pragma unroll
    for (int o = 16; o; o >>= 1) {
        cnt += __shfl_down_sync(0xffffffffu, cnt, o);
        sum += __shfl_down_sync(0xffffffffu, sum, o);
    }
    const int wid  = tid >> 5;
    const int lane = tid & 31;
    if (lane == 0) { red[wid][0] = cnt; red[wid][1] = sum; }
    __syncthreads();

    if (tid == 0) {
        float c2 = 0.f, s2 = 0.f;
        #pragma unroll
        for (int w = 0; w < 9; ++w) { c2 += red[w][0]; s2 += red[w][1]; }
        const int ai = isPred ? 0 : 2;
        atomicAdd(&g_acc[ai],     (double)c2);
        atomicAdd(&g_acc[ai + 1], (double)s2);
        __threadfence();
        unsigned t = atomicAdd(&g_ticket, 1u);
        if (t == NBLK - 1) {
            // last block: finalize, write output, reset for next graph replay
            __threadfence();
            double cp = atomicAdd(&g_acc[0], 0.0);
            double sp = atomicAdd(&g_acc[1], 0.0);
            double ct = atomicAdd(&g_acc[2], 0.0);
            double st = atomicAdd(&g_acc[3], 0.0);
            const double eps = 1e-8;
            double mean_p = (sp + eps * cp) / fmax(cp, 1.0);
            double mean_t = (st + eps * ct) / fmax(ct, 1.0);
            double comp_p = cp / mean_p;
            double comp_t = ct / mean_t;
            float loss = (float)fabs(comp_p - comp_t);  // skeleton_loss == 0 exactly
            for (int i = 0; i < out_size; ++i) out[i] = loss;
            g_acc[0] = 0.0; g_acc[1] = 0.0; g_acc[2] = 0.0; g_acc[3] = 0.0;
            __threadfence();
            g_ticket = 0u;
        }
    }
}

extern "C" void kernel_launch(void* const* d_in, const int* in_sizes, int n_in,
                              void* d_out, int out_size) {
    const float* pred   = (const float*)d_in[0];
    const float* target = (const float*)d_in[1];

    dim3 grid(DIMV / TILE, DIMV / TILE, 16);   // 6 x 6 x 16 = 576 blocks
    fused_skel_kernel<<<grid, NTHR>>>(pred, target, (float*)d_out, out_size);
}

// round 11
// speedup vs baseline: 1.2560x; 1.0023x over previous
#include <cuda_runtime.h>
#include <math.h>

// SoftSkeletonLoss reduces analytically:
//  - soft_skeletonize(sigmoid-range input) == 0 after iteration 1 (conv3x3x3 of a
//    strictly positive field is > 0 -> eroded = opened = 1 -> skeleton = clip(x-1,0,1)=0),
//    so skeleton_loss = 1 - EPS/EPS = 0 exactly.
//  - Remaining: connectivity_loss = |comp_p - comp_t| where
//      comp = cnt / mean_nb,  mean_nb = (sum_masked(conv3x3x3(field)) + EPS*cnt) / max(cnt,1)
//    pred:   field = (pred > 0) binarized (sigmoid(x)>0.5 <=> x>0), mask = pred>0
//    target: field = target raw,                                     mask = target>0
//
// Fused 27-point box-sum reduction. 256 threads (64-reg cap @ 4 CTAs/SM), tile
// 32x24xCHUNK64, two z-planes per barrier with MLP=2 pure-issue prefetch, x-halo
// via warp shuffles at consume time, separable x-presums in smem, and psum's MIDDLE
// row taken from the thread's own registers (2 LDS/plane instead of 3).

#define DIMV   192
#define PLANE  (DIMV * DIMV)
#define TX     32
#define TY     24
#define CHUNK  64
#define HR     26              // halo rows (TY + 2)
#define SP     (HR * 32)       // one xs plane
#define NTHR   256
#define NBLK   (6 * 8 * 12)    // 576 blocks

// cnt_p, sum_p, cnt_t, sum_t (zero at module load; reset by last block each replay)
__device__ double   g_acc[4];
__device__ unsigned g_ticket;

__global__ __launch_bounds__(NTHR, 4)
void fused_skel_kernel(const float* __restrict__ pred,
                       const float* __restrict__ target,
                       float* __restrict__ out, int out_size) {
    __shared__ float sxs[2][2][SP];   // [buf][plane][row*32+col]
    __shared__ float red[8][2];

    const int tid = threadIdx.x;
    const int bx0 = blockIdx.x * TX;
    const int by0 = blockIdx.y * TY;

    const int  zc     = blockIdx.z;            // 0..11
    const bool isPred = (zc < 6);
    const int  s      = isPred ? zc : zc - 6;  // 0..5
    const int  n      = s / 3;                 // sample 0..1
    const int  z0     = (s % 3) * CHUNK;

    const float* __restrict__ src =
        (isPred ? pred : target) + (size_t)n * ((size_t)DIMV * PLANE);

    // ---- loader identity: tid<208 loads halo row ly = tid>>3, chunk jj ----
    const int  ly    = tid >> 3;               // 0..31 (rows 0..25 active)
    const int  jj    = tid & 7;
    const bool lact  = (tid < 8 * HR);         // 208 loader threads
    const int  gy    = by0 + ly - 1;
    const bool rowIn = lact && ((unsigned)gy < (unsigned)DIMV);
    const bool ldE   = ((jj == 0) && (bx0 > 0)) || ((jj == 7) && (bx0 + TX < DIMV));
    const int  eOff  = (jj == 0) ? -1 : 4;
    const int  xsOff = ly * 32 + 4 * jj;

    int zf = z0 - 1;   // first plane of next fetch pair
    const float* lp = src + (long long)zf * PLANE + gy * DIMV + (bx0 + 4 * jj);

    float4 v0, v1;     // raw chunks of the two most recently fetched planes
    float  e0, e1;     // boundary edge scalars

    // PURE-ISSUE fetch of planes zf, zf+1 (nothing consumes results here)
    auto fetch2 = [&]() {
        const bool a0 = rowIn && ((unsigned)zf       < (unsigned)DIMV);
        const bool a1 = rowIn && ((unsigned)(zf + 1) < (unsigned)DIMV);
        v0 = make_float4(0.f, 0.f, 0.f, 0.f); e0 = 0.f;
        v1 = make_float4(0.f, 0.f, 0.f, 0.f); e1 = 0.f;
        if (a0) { v0 = *(const float4*)lp; if (ldE) e0 = lp[eOff]; }
        if (a1) { const float* q = lp + PLANE;
                  v1 = *(const float4*)q; if (ldE) e1 = q[eOff]; }
        lp += 2 * PLANE; zf += 2;
    };

    // consume-time: x-halo shuffles + binarize (pred) + store 3-wide x-sums.
    // RETURNS the xs (kept in registers: it is the psum middle row).
    auto store_xs = [&](const float4& v, float e, float* dst) -> float4 {
        float up = __shfl_up_sync(0xffffffffu, v.w, 1);   // col gx0-1
        float dn = __shfl_down_sync(0xffffffffu, v.x, 1); // col gx0+4
        float el = (jj == 0) ? e : up;
        float er = (jj == 7) ? e : dn;
        float a0, a1, a2, a3, b0, b1;
        if (isPred) {
            a0 = v.x > 0.f ? 1.f : 0.f; a1 = v.y > 0.f ? 1.f : 0.f;
            a2 = v.z > 0.f ? 1.f : 0.f; a3 = v.w > 0.f ? 1.f : 0.f;
            b0 = el  > 0.f ? 1.f : 0.f; b1 = er  > 0.f ? 1.f : 0.f;
        } else { a0 = v.x; a1 = v.y; a2 = v.z; a3 = v.w; b0 = el; b1 = er; }
        float4 xs = make_float4(b0 + a0 + a1, a0 + a1 + a2,
                                a1 + a2 + a3, a2 + a3 + b1);
        if (lact) *(float4*)(dst + xsOff) = xs;
        return xs;
    };

    // ---- compute identity: tid in [8, 200) -> voxel row ty = ly-1 (0..23) ----
    const bool cact = (tid >= 8) && (tid < 8 + 8 * TY);
    const int  ty   = ly - 1;

    auto mask4 = [&](const float4& c) -> int {
        if (!cact) return 0;
        return (c.x > 0.f ? 1 : 0) | (c.y > 0.f ? 2 : 0) |
               (c.z > 0.f ? 4 : 0) | (c.w > 0.f ? 8 : 0);
    };

    // psum: up/down rows from smem, middle row from the thread's own xs regs
    auto psum = [&](const float* sp, const float4& mid) -> float4 {
        if (!cact) return make_float4(0.f, 0.f, 0.f, 0.f);
        float4 a = *(const float4*)(sp + (ty    ) * 32 + 4 * jj);  // row ly-1
        float4 c = *(const float4*)(sp + (ty + 2) * 32 + 4 * jj);  // row ly+1
        return make_float4(a.x + mid.x + c.x, a.y + mid.y + c.y,
                           a.z + mid.z + c.z, a.w + mid.w + c.w);
    };

    // ---- prologue: planes z0-1, z0 -> buf0; prefetch z0+1, z0+2 ----
    fetch2();
    float4 xsp0 = store_xs(v0, e0, sxs[0][0]);
    float4 xsp1 = store_xs(v1, e1, sxs[0][1]);
    int mA = mask4(v1);               // centers of plane z0
    fetch2();
    __syncthreads();
    float4 pA = psum(sxs[0][0], xsp0);   // P(z0-1)
    float4 pB = psum(sxs[0][1], xsp1);   // P(z0)

    float cnt = 0.f, sum = 0.f;

    // ---- main sweep: iteration k handles voxel planes z0+2k, z0+2k+1 ----
    #pragma unroll 2
    for (int k = 0; k < CHUNK / 2; ++k) {
        const int b  = (k + 1) & 1;           // destination buffer
        const int mB = mask4(v0);             // centers plane z+1
        const int mC = mask4(v1);             // centers plane z+2
        float4 xs0 = store_xs(v0, e0, sxs[b][0]);   // xs of plane z+1
        float4 xs1 = store_xs(v1, e1, sxs[b][1]);   // xs of plane z+2
        if (k != CHUNK / 2 - 1) fetch2();     // prefetch planes z+3, z+4
        __syncthreads();
        float4 pC = psum(sxs[b][0], xs0);     // P(z+1)
        float4 pD = psum(sxs[b][1], xs1);     // P(z+2)

        // voxel plane z (mask mA): pA+pB+pC ; plane z+1 (mask mB): pB+pC+pD
        if (mA & 1) { cnt += 1.f; sum += pA.x + pB.x + pC.x; }
        if (mA & 2) { cnt += 1.f; sum += pA.y + pB.y + pC.y; }
        if (mA & 4) { cnt += 1.f; sum += pA.z + pB.z + pC.z; }
        if (mA & 8) { cnt += 1.f; sum += pA.w + pB.w + pC.w; }
        if (mB & 1) { cnt += 1.f; sum += pB.x + pC.x + pD.x; }
        if (mB & 2) { cnt += 1.f; sum += pB.y + pC.y + pD.y; }
        if (mB & 4) { cnt += 1.f; sum += pB.z + pC.z + pD.z; }
        if (mB & 8) { cnt += 1.f; sum += pB.w + pC.w + pD.w; }

        pA = pC; pB = pD; mA = mC;
    }

    // ---- block reduction (8 warps) ----
    #pragma unroll
    for (int o = 16; o; o >>= 1) {
        cnt += __shfl_down_sync(0xffffffffu, cnt, o);
        sum += __shfl_down_sync(0xffffffffu, sum, o);
    }
    const int wid  = tid >> 5;
    const int lane = tid & 31;
    if (lane == 0) { red[wid][0] = cnt; red[wid][1] = sum; }
    __syncthreads();

    if (tid == 0) {
        float c2 = 0.f, s2 = 0.f;
        #pragma unroll
        for (int w = 0; w < 8; ++w) { c2 += red[w][0]; s2 += red[w][1]; }
        const int ai = isPred ? 0 : 2;
        atomicAdd(&g_acc[ai],     (double)c2);
        atomicAdd(&g_acc[ai + 1], (double)s2);
        __threadfence();
        unsigned t = atomicAdd(&g_ticket, 1u);
        if (t == NBLK - 1) {
            // last block: finalize, write output, reset for next graph replay
            __threadfence();
            double cp = atomicAdd(&g_acc[0], 0.0);
            double sp = atomicAdd(&g_acc[1], 0.0);
            double ct = atomicAdd(&g_acc[2], 0.0);
            double st = atomicAdd(&g_acc[3], 0.0);
            const double eps = 1e-8;
            double mean_p = (sp + eps * cp) / fmax(cp, 1.0);
            double mean_t = (st + eps * ct) / fmax(ct, 1.0);
            double comp_p = cp / mean_p;
            double comp_t = ct / mean_t;
            float loss = (float)fabs(comp_p - comp_t);  // skeleton_loss == 0 exactly
            for (int i = 0; i < out_size; ++i) out[i] = loss;
            g_acc[0] = 0.0; g_acc[1] = 0.0; g_acc[2] = 0.0; g_acc[3] = 0.0;
            __threadfence();
            g_ticket = 0u;
        }
    }
}

extern "C" void kernel_launch(void* const* d_in, const int* in_sizes, int n_in,
                              void* d_out, int out_size) {
    const float* pred   = (const float*)d_in[0];
    const float* target = (const float*)d_in[1];

    dim3 grid(DIMV / TX, DIMV / TY, 12);   // 6 x 8 x 12 = 576 blocks
    fused_skel_kernel<<<grid, NTHR>>>(pred, target, (float*)d_out, out_size);
}